// round 15
// baseline (speedup 1.0000x reference)
#include <cuda_runtime.h>
#include <cuda_fp16.h>
#include <math.h>
#include <stdint.h>

constexpr int NN   = 20000;
constexpr int NE   = 200000;
constexpr int IND  = 2000;
constexpr int EMBD = 512;
constexpr float BN_S = 0.9999950000374997f;
constexpr int MP = 20096;                 // 157*128
#define CDIV(a,b) (((a)+(b)-1)/(b))
constexpr int FL_RELU = 1, FL_SCALE = 2;

// ---------------- fp32 scratch ----------------
constexpr size_t F_DPP = 0;
constexpr size_t F_NA  = F_DPP + NE;
constexpr size_t F_NB  = F_NA  + NE;
constexpr size_t F_Z   = F_NB  + NE;                        // [NN,256]
constexpr size_t F_A48 = F_Z   + (size_t)NN*256;
constexpr size_t F_V32 = F_A48 + (size_t)NN*48;
constexpr size_t F_P16 = F_V32 + (size_t)NN*32;             // adjacent to V32
constexpr size_t F_ESQ = F_P16 + (size_t)NN*16;
constexpr size_t F_EW  = F_ESQ + NN;
constexpr size_t F_DEG = F_EW  + NE;
constexpr size_t F_NRM = F_DEG + NN;
constexpr size_t F_WT  = F_NRM + NE;
constexpr size_t F_TOTAL = F_WT + (size_t)48*512;
__device__ __align__(256) float g_f[F_TOTAL];

// ---------------- fp16 arena ----------------
constexpr size_t H_IMG = 0;                                  // [MP,4032]  (h,l)
constexpr size_t H_EIW = H_IMG + (size_t)MP*4032;            // [512,4032] dup
constexpr size_t H_ESW = H_EIW + (size_t)512*4032;           // contiguous
constexpr size_t H_EIES= H_ESW + (size_t)512*4032;           // [MP,2048]  (h,l)
constexpr size_t H_JKS = H_EIES+ (size_t)MP*2048;            // [MP,128]   (h,l)
constexpr size_t H_DEW = H_JKS + (size_t)MP*128;             // [512,2048] dup
constexpr size_t H_S1W = H_DEW + (size_t)512*2048;           // [256,1024] dup
constexpr size_t H_CH  = H_S1W + (size_t)256*1024;           // [64,1024]  dup (contiguous)
constexpr size_t H_L1W = H_CH  + (size_t)64*1024;            // [256,128]  dup
constexpr size_t H_P2W = H_L1W + (size_t)256*128;            // [128,256]  (h,l)
constexpr size_t H_TOTAL = H_P2W + (size_t)128*256 + 4096;
__device__ __align__(256) __half g_h[H_TOTAL];

// ---------------- streams/events ----------------
static cudaStream_t g_sP, g_sR, g_sS;
static cudaEvent_t g_evFork, g_evES, g_evEnc, g_evNrm, g_evS, g_evRec;
namespace {
struct StreamInit {
    StreamInit(){
        cudaStreamCreateWithFlags(&g_sP, cudaStreamNonBlocking);
        cudaStreamCreateWithFlags(&g_sR, cudaStreamNonBlocking);
        cudaStreamCreateWithFlags(&g_sS, cudaStreamNonBlocking);
        cudaEventCreateWithFlags(&g_evFork, cudaEventDisableTiming);
        cudaEventCreateWithFlags(&g_evES,   cudaEventDisableTiming);
        cudaEventCreateWithFlags(&g_evEnc,  cudaEventDisableTiming);
        cudaEventCreateWithFlags(&g_evNrm,  cudaEventDisableTiming);
        cudaEventCreateWithFlags(&g_evS,    cudaEventDisableTiming);
        cudaEventCreateWithFlags(&g_evRec,  cudaEventDisableTiming);
    }
};
StreamInit s_streamInit;
}

// ---------------- PTX helpers ----------------
__device__ __forceinline__ uint32_t smem_u32(const void* p){
    uint32_t a; asm("{ .reg .u64 t; cvta.to.shared.u64 t, %1; cvt.u32.u64 %0, t; }" : "=r"(a) : "l"(p)); return a;
}
__device__ __forceinline__ void cp_async16(uint32_t dst, const void* src){
    asm volatile("cp.async.cg.shared.global [%0], [%1], 16;" :: "r"(dst), "l"(src));
}
__device__ __forceinline__ void cp_commit(){ asm volatile("cp.async.commit_group;" ::: "memory"); }
__device__ __forceinline__ void cp_wait0(){ asm volatile("cp.async.wait_group 0;" ::: "memory"); }
__device__ __forceinline__ void ldmx4(uint32_t* r, uint32_t addr){
    asm volatile("ldmatrix.sync.aligned.m8n8.x4.shared.b16 {%0,%1,%2,%3}, [%4];"
        : "=r"(r[0]),"=r"(r[1]),"=r"(r[2]),"=r"(r[3]) : "r"(addr));
}
__device__ __forceinline__ void mma16816(float* d, const uint32_t* a, const uint32_t* b){
    asm volatile("mma.sync.aligned.m16n8k16.row.col.f32.f16.f16.f32 "
        "{%0,%1,%2,%3}, {%4,%5,%6,%7}, {%8,%9}, {%0,%1,%2,%3};"
        : "+f"(d[0]),"+f"(d[1]),"+f"(d[2]),"+f"(d[3])
        : "r"(a[0]),"r"(a[1]),"r"(a[2]),"r"(a[3]), "r"(b[0]),"r"(b[1]));
}

// ---------------- fp16 HMMA GEMM, BM=128/BN=128/BK=32, one sync per iter ----------------
__global__ void __launch_bounds__(256, 2)
mma_gemm(const __half* __restrict__ A, int lda,
         const __half* __restrict__ B, int ldb,
         const float* __restrict__ bias,
         float* __restrict__ C, int ldc,
         int M, int N, int Kp, int flags,
         int Nsplit, const float* __restrict__ bias2,
         float* __restrict__ C2, int ldc2, int flags2,
         int epimode, __half* __restrict__ SP, float* __restrict__ esqp)
{
    __shared__ __align__(128) __half As[2][128*32];
    __shared__ __align__(128) __half Bs[2][128*32];
    const int tid = threadIdx.x;
    const int lane = tid & 31, wid = tid >> 5;
    const int wm = wid >> 1, wn = wid & 1;
    const int bm = blockIdx.y * 128, bn = blockIdx.x * 128;
    const uint32_t as0 = smem_u32(As), bs0 = smem_u32(Bs);

    float acc[2][8][4];
#pragma unroll
    for (int i = 0; i < 2; i++)
#pragma unroll
        for (int j = 0; j < 8; j++)
#pragma unroll
            for (int k = 0; k < 4; k++) acc[i][j][k] = 0.f;

    const int a_row_l = lane & 15, a_cb = lane >> 4;
    const int g = lane >> 3, b_row_l = ((g >> 1) & 1) * 8 + (lane & 7), b_cb = g & 1;

    auto loadAB = [&](int buf, int k0){
#pragma unroll
        for (int j = 0; j < 2; j++){
            int u = tid * 2 + j;
            int row = u >> 2, c = u & 3;
            int cs = c ^ ((row >> 1) & 3);
            cp_async16(as0 + (uint32_t)(buf*8192 + row*64 + cs*16),
                       A + (size_t)(bm + row) * lda + k0 + c*8);
            cp_async16(bs0 + (uint32_t)(buf*8192 + row*64 + cs*16),
                       B + (size_t)(bn + row) * ldb + k0 + c*8);
        }
        cp_commit();
    };

    const int nk = Kp >> 5;
    loadAB(0, 0);
    for (int i = 0; i < nk; i++){
        const int buf = i & 1;
        cp_wait0();
        __syncthreads();
        if (i + 1 < nk) loadAB(buf ^ 1, (i+1) * 32);
#pragma unroll
        for (int kk = 0; kk < 2; kk++){
            uint32_t afr[2][4], bfr[4][4];
#pragma unroll
            for (int mi = 0; mi < 2; mi++){
                int row = wm*32 + mi*16 + a_row_l;
                int c = kk*2 + a_cb;
                int cs = c ^ ((row >> 1) & 3);
                ldmx4(afr[mi], as0 + (uint32_t)(buf*8192 + row*64 + cs*16));
            }
#pragma unroll
            for (int nh = 0; nh < 4; nh++){
                int row = wn*64 + nh*16 + b_row_l;
                int c = kk*2 + b_cb;
                int cs = c ^ ((row >> 1) & 3);
                ldmx4(bfr[nh], bs0 + (uint32_t)(buf*8192 + row*64 + cs*16));
            }
#pragma unroll
            for (int mi = 0; mi < 2; mi++)
#pragma unroll
                for (int ni = 0; ni < 8; ni++)
                    mma16816(acc[mi][ni], afr[mi], &bfr[ni>>1][(ni&1)*2]);
        }
    }

    if (epimode == 1){
        // ES half: Nsplit=0 -> is_es always; EI half: Nsplit huge -> never.
        const bool is_es = (bn >= Nsplit);
        const float* bs = is_es ? bias2 : bias;
        const int cb = bn - (is_es ? Nsplit : 0) + wn*64;
        uint32_t* SPw = (uint32_t*)SP;
#pragma unroll
        for (int mi = 0; mi < 2; mi++){
#pragma unroll
            for (int h = 0; h < 2; h++){
                int row = bm + wm*32 + mi*16 + (lane >> 2) + h*8;
                bool rok = row < M;
                float sq = 0.f;
#pragma unroll
                for (int ni = 0; ni < 8; ni++){
                    int c = cb + ni*8 + (lane & 3)*2;
                    float v0 = acc[mi][ni][h*2+0] + bs[c];
                    float v1 = acc[mi][ni][h*2+1] + bs[c+1];
                    if (rok){
                        if (is_es){
                            C2[(size_t)row*ldc2 + c]   = v0;
                            C2[(size_t)row*ldc2 + c+1] = v1;
                            sq += v0*v0 + v1*v1;
                        }
                        __half h0 = __float2half(v0);
                        __half l0 = __float2half(v0 - __half2float(h0));
                        __half h1 = __float2half(v1);
                        __half l1 = __float2half(v1 - __half2float(h1));
                        size_t wi = (size_t)row*1024 + (is_es ? 512 : 0) + c;
                        SPw[wi]   = (uint32_t)__half_as_ushort(h0) | ((uint32_t)__half_as_ushort(l0) << 16);
                        SPw[wi+1] = (uint32_t)__half_as_ushort(h1) | ((uint32_t)__half_as_ushort(l1) << 16);
                    }
                }
                if (is_es){
                    sq += __shfl_xor_sync(0xffffffffu, sq, 1);
                    sq += __shfl_xor_sync(0xffffffffu, sq, 2);
                    if (rok && (lane & 3) == 0) atomicAdd(&esqp[row], sq);
                }
            }
        }
        return;
    }

    const float sc1 = (flags  & FL_SCALE) ? BN_S : 1.f;
    const float sc2 = (flags2 & FL_SCALE) ? BN_S : 1.f;
#pragma unroll
    for (int mi = 0; mi < 2; mi++){
#pragma unroll
        for (int ni = 0; ni < 8; ni++){
            int col = bn + wn*64 + ni*8 + (lane & 3) * 2;
#pragma unroll
            for (int h = 0; h < 2; h++){
                int row = bm + wm*32 + mi*16 + (lane >> 2) + h*8;
                if (row < M){
#pragma unroll
                    for (int q = 0; q < 2; q++){
                        int cc = col + q;
                        if (cc < N){
                            float v = acc[mi][ni][h*2 + q];
                            if (cc < Nsplit){
                                if (bias) v += bias[cc];
                                if (flags & FL_RELU) v = fmaxf(v, 0.f);
                                C[(size_t)row * ldc + cc] = v * sc1;
                            } else {
                                int c2 = cc - Nsplit;
                                if (bias2) v += bias2[c2];
                                if (flags2 & FL_RELU) v = fmaxf(v, 0.f);
                                C2[(size_t)row * ldc2 + c2] = v * sc2;
                            }
                        }
                    }
                }
            }
        }
    }
}

// ---------------- fused edge parser (unchanged) ----------------
constexpr int P_HROW = 264;
constexpr int P_HB   = 128 * P_HROW * 2;
constexpr int P_WOFF = P_HB;
constexpr int P_P1   = P_WOFF + 16384;
constexpr int P_P2B  = P_P1 + 2048;
constexpr int P_EACC = P_P2B + 512;
constexpr int PAR_SMEM = P_EACC + 1024 + 256;
__global__ void __launch_bounds__(256, 2)
parser_edge_kernel(const float* __restrict__ nif,
                   const float* __restrict__ p1w, const float* __restrict__ p1b,
                   const __half* __restrict__ W2s, const float* __restrict__ p2b,
                   float* __restrict__ dppA, float* __restrict__ naA, float* __restrict__ nbA)
{
    extern __shared__ char sm[];
    uint32_t* Hs32 = (uint32_t*)sm;
    const uint32_t base = smem_u32(sm);
    const uint32_t wsb  = base + P_WOFF;
    float* p1s  = (float*)(sm + P_P1);
    float* p2bs = (float*)(sm + P_P2B);
    float* eacc = (float*)(sm + P_EACC);

    const int tid = threadIdx.x, lane = tid & 31, wid = tid >> 5;
    const int wm = wid >> 1, wn = wid & 1;
    const int e0 = blockIdx.x * 64;

    for (int i = tid; i < 512; i += 256)
        p1s[i] = (i < 384) ? p1w[i] : p1b[i - 384];
    if (tid < 128) p2bs[tid] = p2b[tid];
    if (tid < 64) { eacc[tid*4] = 0.f; eacc[tid*4+1] = 0.f; eacc[tid*4+2] = 0.f; }
    __syncthreads();

    {
        int r = tid >> 1, hh = tid & 1;
        int e = e0 + (r >> 1), side = r & 1;
        const float* x = nif + (size_t)e*6 + side*3;
        float x0 = x[0], x1 = x[1], x2 = x[2];
#pragma unroll
        for (int j = 0; j < 64; j++){
            int ju = hh*64 + j;
            float v = fmaf(p1s[ju*3+2], x2, fmaf(p1s[ju*3+1], x1, fmaf(p1s[ju*3], x0, p1s[384+ju])));
            v = fmaxf(v, 0.f) * BN_S;
            uint32_t hb = (uint32_t)__half_as_ushort(__float2half(v));
            Hs32[r*(P_HROW/2) + ju] = hb | (hb << 16);
        }
    }

    auto loadW = [&](int buf, int k0){
#pragma unroll
        for (int j = 0; j < 2; j++){
            int u = tid*2 + j;
            int row = u >> 2, c = u & 3;
            int cs = c ^ ((row >> 1) & 3);
            cp_async16(wsb + (uint32_t)(buf*8192 + row*64 + cs*16),
                       W2s + (size_t)row*256 + k0 + c*8);
        }
        cp_commit();
    };
    loadW(0, 0);

    float acc[2][8][4];
#pragma unroll
    for (int i = 0; i < 2; i++)
#pragma unroll
        for (int j = 0; j < 8; j++)
#pragma unroll
            for (int k = 0; k < 4; k++) acc[i][j][k] = 0.f;

    const int a_row_l = lane & 15, a_cb = lane >> 4;
    const int g = lane >> 3, b_row_l = ((g>>1)&1)*8 + (lane&7), b_cb = g & 1;

    for (int i = 0; i < 8; i++){
        const int buf = i & 1;
        cp_wait0();
        __syncthreads();
        if (i + 1 < 8) loadW(buf ^ 1, (i+1)*32);
#pragma unroll
        for (int kk = 0; kk < 2; kk++){
            uint32_t afr[2][4], bfr[4][4];
#pragma unroll
            for (int mi = 0; mi < 2; mi++){
                int row = wm*32 + mi*16 + a_row_l;
                int chunk = (i*2 + kk)*2 + a_cb;
                ldmx4(afr[mi], base + (uint32_t)(row*(P_HROW*2) + chunk*16));
            }
#pragma unroll
            for (int nh = 0; nh < 4; nh++){
                int row = wn*64 + nh*16 + b_row_l;
                int c = kk*2 + b_cb;
                int cs = c ^ ((row >> 1) & 3);
                ldmx4(bfr[nh], wsb + (uint32_t)(buf*8192 + row*64 + cs*16));
            }
#pragma unroll
            for (int mi = 0; mi < 2; mi++)
#pragma unroll
                for (int ni = 0; ni < 8; ni++)
                    mma16816(acc[mi][ni], afr[mi], &bfr[ni>>1][(ni&1)*2]);
        }
    }

#pragma unroll
    for (int mi = 0; mi < 2; mi++){
#pragma unroll
        for (int h = 0; h < 2; h++){
            float pd = 0.f, pq = 0.f;
#pragma unroll
            for (int ni = 0; ni < 8; ni++){
#pragma unroll
                for (int q = 0; q < 2; q++){
                    int col = wn*64 + ni*8 + (lane & 3)*2 + q;
                    float p = acc[mi][ni][h*2 + q] + p2bs[col];
                    float pp = __shfl_xor_sync(0xffffffffu, p, 4);
                    pd += p * pp;
                    pq += p * p;
                }
            }
            pd += __shfl_xor_sync(0xffffffffu, pd, 1);
            pd += __shfl_xor_sync(0xffffffffu, pd, 2);
            pq += __shfl_xor_sync(0xffffffffu, pq, 1);
            pq += __shfl_xor_sync(0xffffffffu, pq, 2);
            float nbv = __shfl_xor_sync(0xffffffffu, pq, 4);
            if ((lane & 7) == 0){
                int row = wm*32 + mi*16 + (lane >> 2) + h*8;
                int el = row >> 1;
                atomicAdd(&eacc[el*4 + 0], pd);
                atomicAdd(&eacc[el*4 + 1], pq);
                atomicAdd(&eacc[el*4 + 2], nbv);
            }
        }
    }
    __syncthreads();
    if (tid < 64){
        int e = e0 + tid;
        dppA[e] = eacc[tid*4 + 0];
        naA[e]  = eacc[tid*4 + 1];
        nbA[e]  = eacc[tid*4 + 2];
    }
}

// ---------------- fp16 2-term split (optionally zeroes esq per row) ----------------
__global__ void split_h(const float* __restrict__ src, int lds_, int rows, int K, int KB,
                        __half* __restrict__ dst, int ldd, int mode, float* __restrict__ esq0)
{
    int r = blockIdx.y;
    int t = blockIdx.x * blockDim.x + threadIdx.x;
    if (esq0 && t == 0 && r < rows) esq0[r] = 0.f;
    int kb = t * 2;
    if (kb >= KB) return;
    float x = (r < rows && t < K) ? src[(size_t)r*lds_ + t] : 0.f;
    __half hi = __float2half(x);
    __half sec = mode ? __float2half(x - __half2float(hi)) : hi;
    __half* d = dst + (size_t)r*ldd + kb;
    d[0] = hi; d[1] = sec;
}

// ---------------- small GEMM ----------------
__global__ void gemm_small(const float* __restrict__ A, int lda,
                           const float* __restrict__ B, int ldb,
                           const float* __restrict__ bias,
                           float* __restrict__ C, int ldc,
                           int M, int N, int K, int flags)
{
    int idx = blockIdx.x * blockDim.x + threadIdx.x;
    if (idx >= M * N) return;
    int m = idx / N, n = idx - m * N;
    float s = bias ? bias[n] : 0.f;
    const float* a = A + (size_t)m * lda;
    const float* b = B + (size_t)n * ldb;
    for (int k = 0; k < K; k++) s = fmaf(a[k], b[k], s);
    if (flags & FL_RELU) s = fmaxf(s, 0.f);
    if (flags & FL_SCALE) s *= BN_S;
    C[(size_t)m * ldc + n] = s;
}

// ---------------- node/edge kernels ----------------
__global__ void edge_weight_kernel(const int* __restrict__ src, const int* __restrict__ tgt,
                                   const float* __restrict__ dppA, const float* __restrict__ naA,
                                   const float* __restrict__ nbA,
                                   const float* __restrict__ es, const float* __restrict__ es_sq,
                                   float* __restrict__ ew, float* __restrict__ deg)
{
    int w = (blockIdx.x * blockDim.x + threadIdx.x) >> 5;
    int lane = threadIdx.x & 31;
    if (w >= NE) return;
    int s = src[w], t = tgt[w];
    const float4* rs = (const float4*)(es + (size_t)s * EMBD);
    const float4* rt = (const float4*)(es + (size_t)t * EMBD);
    float des = 0.f;
#pragma unroll
    for (int i = lane; i < EMBD/4; i += 32) { float4 a = rs[i], b = rt[i]; des += a.x*b.x+a.y*b.y+a.z*b.z+a.w*b.w; }
#pragma unroll
    for (int o = 16; o; o >>= 1) des += __shfl_down_sync(0xffffffffu, des, o);
    if (lane == 0) {
        float n1 = fmaxf(sqrtf(naA[w] + es_sq[s]), 1e-8f);
        float n2 = fmaxf(sqrtf(nbA[w] + es_sq[t]), 1e-8f);
        float cw = ((dppA[w] + des) / (n1 * n2) + 1.f) * 0.5f;
        ew[w] = cw;
        atomicAdd(&deg[s], cw);
    }
}

// fused dis+norm: rsqrt computed per edge (bitwise same as table)
__global__ void norm_kernel(const int* __restrict__ src, const int* __restrict__ tgt,
                            const float* __restrict__ ew, const float* __restrict__ deg,
                            float* __restrict__ nrm)
{
    int e = blockIdx.x * blockDim.x + threadIdx.x;
    if (e >= NE) return;
    float ds = deg[src[e]], dt = deg[tgt[e]];
    float a = ds > 0.f ? rsqrtf(ds) : 0.f;
    float b = dt > 0.f ? rsqrtf(dt) : 0.f;
    nrm[e] = a * ew[e] * b;
}

// prop with float4 gathers + red.global.v4
__global__ void prop_kernel(const int* __restrict__ src, const int* __restrict__ tgt,
                            const float* __restrict__ nrm,
                            const float* __restrict__ Z, int ldz, int offz,
                            float* __restrict__ Out, int width, int lg)
{
    int idx = blockIdx.x * blockDim.x + threadIdx.x;
    if (idx >= (NE << lg)) return;
    int e = idx >> lg;
    int c = (idx & ((1 << lg) - 1)) * 4;
    float s = -nrm[e];
    float4 zv = *(const float4*)&Z[(size_t)src[e] * ldz + offz + c];
    float* o = &Out[(size_t)tgt[e] * width + c];
    asm volatile("red.global.v4.f32.add [%0], {%1, %2, %3, %4};"
                 :: "l"(o), "f"(s*zv.x), "f"(s*zv.y), "f"(s*zv.z), "f"(s*zv.w) : "memory");
}

__global__ void prep_cheb(const float* __restrict__ W, int in_dim, float* __restrict__ Wt)
{
    int idx = blockIdx.x * blockDim.x + threadIdx.x;
    if (idx >= 48 * in_dim) return;
    int n = idx / in_dim, i = idx - n * in_dim;
    float v;
    if (n < 16)       v = W[(0*in_dim + i)*16 + n] - W[(2*in_dim + i)*16 + n];
    else if (n < 32)  v = W[(1*in_dim + i)*16 + (n - 16)];
    else              v = W[(2*in_dim + i)*16 + (n - 32)];
    Wt[(size_t)n * in_dim + i] = v;
}

// fused combine
__global__ void combine_kernel(float* __restrict__ A48, float* __restrict__ V32,
                               float* __restrict__ P16,
                               const float* __restrict__ Wn,
                               __half* __restrict__ jkS, int layer)
{
    int idx = blockIdx.x * blockDim.x + threadIdx.x;
    if (idx >= NN * 16) return;
    int m = idx >> 4, c = idx & 15;
    int lane = threadIdx.x & 31;
    float v = A48[(size_t)m*48 + c] + V32[(size_t)m*32 + c] + 2.f * P16[(size_t)m*16 + c];
    v = fmaxf(v, 0.f);
    __half hi = __float2half(v);
    __half lo = __float2half(v - __half2float(hi));
    __half* d = jkS + (size_t)m*128 + 2*(layer*16 + c);
    d[0] = hi; d[1] = lo;

    if (layer < 3){
        int base = lane & 16;
        float hv[16];
#pragma unroll
        for (int k = 0; k < 16; k++)
            hv[k] = __shfl_sync(0xffffffffu, v, base | k);
#pragma unroll
        for (int j = 0; j < 3; j++){
            int n = 3*c + j;
            float s = 0.f;
            if (n < 16){
#pragma unroll
                for (int k = 0; k < 16; k++)
                    s = fmaf(hv[k], Wn[k*16 + n] - Wn[512 + k*16 + n], s);
            } else if (n < 32){
                int nn = n - 16;
#pragma unroll
                for (int k = 0; k < 16; k++)
                    s = fmaf(hv[k], Wn[256 + k*16 + nn], s);
            } else {
                int nn = n - 32;
#pragma unroll
                for (int k = 0; k < 16; k++)
                    s = fmaf(hv[k], Wn[512 + k*16 + nn], s);
            }
            A48[(size_t)m*48 + n] = s;
        }
        V32[(size_t)m*32 + c] = 0.f;
        V32[(size_t)m*32 + c + 16] = 0.f;
        P16[(size_t)m*16 + c] = 0.f;
    }
}

// ---------------- launch ----------------
extern "C" void kernel_launch(void* const* d_in, const int* in_sizes, int n_in,
                              void* d_out, int out_size)
{
    const float* img   = (const float*)d_in[0];
    const int*   eidx  = (const int*)d_in[1];
    const float* nif   = (const float*)d_in[2];
    const float* EI_w  = (const float*)d_in[3];
    const float* EI_b  = (const float*)d_in[4];
    const float* ES_w  = (const float*)d_in[5];
    const float* ES_b  = (const float*)d_in[6];
    const float* DE_w  = (const float*)d_in[7];
    const float* DE_b  = (const float*)d_in[8];
    const float* chw[4] = {(const float*)d_in[9], (const float*)d_in[10],
                           (const float*)d_in[11], (const float*)d_in[12]};
    const float* l1_w  = (const float*)d_in[13];
    const float* l1_b  = (const float*)d_in[14];
    const float* l2_w  = (const float*)d_in[15];
    const float* l2_b  = (const float*)d_in[16];
    const float* s1_w  = (const float*)d_in[17];
    const float* s1_b  = (const float*)d_in[18];
    const float* s2_w  = (const float*)d_in[19];
    const float* s2_b  = (const float*)d_in[20];
    const float* p1_w  = (const float*)d_in[21];
    const float* p1_b  = (const float*)d_in[22];
    const float* p2_w  = (const float*)d_in[23];
    const float* p2_b  = (const float*)d_in[24];

    float* F = nullptr; cudaGetSymbolAddress((void**)&F, g_f);
    __half* Hh = nullptr; cudaGetSymbolAddress((void**)&Hh, g_h);

    float* dpp = F + F_DPP; float* na  = F + F_NA;  float* nb  = F + F_NB;
    float* z   = F + F_Z;   float* A48 = F + F_A48; float* V32 = F + F_V32;
    float* P16 = F + F_P16; float* esq = F + F_ESQ; float* ew  = F + F_EW;
    float* deg = F + F_DEG; float* nrm = F + F_NRM; float* Wt  = F + F_WT;

    __half* imgS = Hh + H_IMG;  __half* EIwS = Hh + H_EIW;  __half* ESwS = Hh + H_ESW;
    __half* eies = Hh + H_EIES; __half* jkS  = Hh + H_JKS;  __half* DEwH = Hh + H_DEW;
    __half* s1wH = Hh + H_S1W;  __half* chH  = Hh + H_CH;   __half* l1wH = Hh + H_L1W;
    __half* p2wH = Hh + H_P2W;

    float* out_label = (float*)d_out;
    float* out_site  = out_label + (size_t)NN * 2;
    float* out_es    = out_site  + (size_t)NN * 20;
    float* out_rec   = out_es    + (size_t)NN * 512;

    const int* srcp = eidx;
    const int* tgtp = eidx + NE;

    dim3 blk(256);
    cudaFuncSetAttribute(parser_edge_kernel, cudaFuncAttributeMaxDynamicSharedMemorySize, PAR_SMEM);

    auto splitsH = [&](const float* s, int lds_, int rows, int rp, int K, int KB,
                       __half* d, int ldd, int mode, cudaStream_t st, float* esq0 = nullptr) {
        dim3 gg(CDIV(KB/2, 256), rp);
        split_h<<<gg, blk, 0, st>>>(s, lds_, rows, K, KB, d, ldd, mode, esq0);
    };

    // 1: p2w split, fork
    splitsH(p2_w, 128, 128, 128, 128, 256, p2wH, 256, 1, 0);
    cudaEventRecord(g_evFork, 0);

    // 2: parser on sP (concurrent with both encoder halves)
    cudaStreamWaitEvent(g_sP, g_evFork, 0);
    parser_edge_kernel<<<NE/64, blk, PAR_SMEM, g_sP>>>(nif, p1_w, p1_b, p2wH, p2_b, dpp, na, nb);

    // 3-5: ES-GEMM deps on main (img split also zeroes esq)
    splitsH(ES_w, IND, 512, 512, IND, 4032, ESwS, 4032, 0, 0);
    splitsH(img, IND, NN, MP, IND, 4032, imgS, 4032, 1, 0, esq);
    splitsH(EI_w, IND, 512, 512, IND, 4032, EIwS, 4032, 0, 0);

    // 6: ES half (Nsplit=0 -> all-es path: out_es fp32 + eies[:,1024:] + esq)
    mma_gemm<<<dim3(4,157), blk>>>(imgS, 4032, ESwS, 4032, nullptr, nullptr, 0,
                                   NN, 512, 4032, 0, 0, ES_b, out_es, 512, 0,
                                   1, eies, esq);
    cudaEventRecord(g_evES, 0);

    // 7: EI half (Nsplit huge -> all-ei path: eies[:,0:1024] only)
    mma_gemm<<<dim3(4,157), blk>>>(imgS, 4032, EIwS, 4032, EI_b, nullptr, 0,
                                   NN, 512, 4032, 0, 1 << 30, nullptr, nullptr, 0, 0,
                                   1, eies, esq);
    cudaEventRecord(g_evEnc, 0);

    // sP: edge chain right after ES half (concurrent with EI half)
    cudaMemsetAsync(deg, 0, NN * sizeof(float), g_sP);
    cudaStreamWaitEvent(g_sP, g_evES, 0);
    edge_weight_kernel<<<CDIV(NE*32,256), blk, 0, g_sP>>>(srcp, tgtp, dpp, na, nb, out_es, esq, ew, deg);
    norm_kernel<<<CDIV(NE,256), blk, 0, g_sP>>>(srcp, tgtp, ew, deg, nrm);
    cudaEventRecord(g_evNrm, g_sP);

    // sR: DE split (overlaps encoder) then rec
    cudaStreamWaitEvent(g_sR, g_evFork, 0);
    splitsH(DE_w, 1024, 512, 512, 1024, 2048, DEwH, 2048, 0, g_sR);
    cudaStreamWaitEvent(g_sR, g_evEnc, 0);
    mma_gemm<<<dim3(4,157), blk, 0, g_sR>>>(eies, 2048, DEwH, 2048, DE_b, out_rec, 512,
                                   NN, 512, 2048, 0, 512, nullptr, nullptr, 0, 0,
                                   0, nullptr, nullptr);
    cudaEventRecord(g_evRec, g_sR);

    // sS: s1/cheb0 weight prep (overlaps encoder) then fused s1+cheb0, site head
    cudaStreamWaitEvent(g_sS, g_evFork, 0);
    splitsH(s1_w, 512, 256, 256, 512, 1024, s1wH, 1024, 0, g_sS);
    prep_cheb<<<CDIV(48*512,256), blk, 0, g_sS>>>(chw[0], 512, Wt);
    splitsH(Wt, 512, 48, 64, 512, 1024, chH, 1024, 0, g_sS);
    cudaStreamWaitEvent(g_sS, g_evEnc, 0);
    mma_gemm<<<dim3(3,157), blk, 0, g_sS>>>(eies, 2048, s1wH, 1024, s1_b, z, 256,
                                   NN, 304, 1024, FL_RELU|FL_SCALE, 256, nullptr, A48, 48, 0,
                                   0, nullptr, nullptr);
    gemm_small<<<CDIV(NN*20,256), blk, 0, g_sS>>>(z, 256, s2_w, 256, s2_b, out_site, 20, NN, 20, 256, 0);
    cudaEventRecord(g_evS, g_sS);

    // main: remaining prep + cheb loop + label head
    cudaMemsetAsync(V32, 0, (size_t)NN*48*sizeof(float));    // V32+P16, layer 0
    splitsH(l1_w, 64, 256, 256, 64, 128, l1wH, 128, 0, 0);
    cudaStreamWaitEvent(0, g_evS, 0);
    cudaStreamWaitEvent(0, g_evNrm, 0);
    for (int layer = 0; layer < 4; layer++) {
        prop_kernel<<<CDIV(NE*8,256), blk>>>(srcp, tgtp, nrm, A48, 48, 16, V32, 32, 3);
        prop_kernel<<<CDIV(NE*4,256), blk>>>(srcp, tgtp, nrm, V32, 32, 16, P16, 16, 2);
        combine_kernel<<<CDIV(NN*16,256), blk>>>(A48, V32, P16,
                                                 (layer < 3) ? chw[layer+1] : chw[0], jkS, layer);
    }

    mma_gemm<<<dim3(2,157), blk>>>(jkS, 128, l1wH, 128, l1_b, z, 256,
                                   NN, 256, 128, FL_RELU|FL_SCALE, 256, nullptr, nullptr, 0, 0,
                                   0, nullptr, nullptr);
    gemm_small<<<CDIV(NN*2,256), blk>>>(z, 256, l2_w, 256, l2_b, out_label, 2, NN, 2, 256, 0);

    cudaStreamWaitEvent(0, g_evRec, 0);
}

// round 16
// speedup vs baseline: 1.0826x; 1.0826x over previous
#include <cuda_runtime.h>
#include <cuda_fp16.h>
#include <math.h>
#include <stdint.h>

constexpr int NN   = 20000;
constexpr int NE   = 200000;
constexpr int IND  = 2000;
constexpr int EMBD = 512;
constexpr float BN_S = 0.9999950000374997f;
constexpr int MP = 20096;                 // 157*128
#define CDIV(a,b) (((a)+(b)-1)/(b))
constexpr int FL_RELU = 1, FL_SCALE = 2;

// ---------------- fp32 scratch ----------------
constexpr size_t F_DPP = 0;
constexpr size_t F_NA  = F_DPP + NE;
constexpr size_t F_NB  = F_NA  + NE;
constexpr size_t F_Z   = F_NB  + NE;                        // [NN,256]
constexpr size_t F_A48 = F_Z   + (size_t)NN*256;
constexpr size_t F_V32 = F_A48 + (size_t)NN*48;
constexpr size_t F_P16 = F_V32 + (size_t)NN*32;             // adjacent to V32
constexpr size_t F_ESQ = F_P16 + (size_t)NN*16;
constexpr size_t F_EW  = F_ESQ + NN;
constexpr size_t F_DEG = F_EW  + NE;
constexpr size_t F_NRM = F_DEG + NN;
constexpr size_t F_WT  = F_NRM + NE;
constexpr size_t F_TOTAL = F_WT + (size_t)48*512;
__device__ __align__(256) float g_f[F_TOTAL];

// ---------------- fp16 arena ----------------
constexpr size_t H_IMG = 0;                                  // [MP,4032]  (h,l)
constexpr size_t H_EIW = H_IMG + (size_t)MP*4032;            // [512,4032] dup
constexpr size_t H_ESW = H_EIW + (size_t)512*4032;           // contiguous
constexpr size_t H_EIES= H_ESW + (size_t)512*4032;           // [MP,2048]  (h,l)
constexpr size_t H_JKS = H_EIES+ (size_t)MP*2048;            // [MP,128]   (h,l)
constexpr size_t H_DEW = H_JKS + (size_t)MP*128;             // [512,2048] dup
constexpr size_t H_S1W = H_DEW + (size_t)512*2048;           // [256,1024] dup
constexpr size_t H_CH  = H_S1W + (size_t)256*1024;           // [64,1024]  dup (contiguous)
constexpr size_t H_L1W = H_CH  + (size_t)64*1024;            // [256,128]  dup
constexpr size_t H_P2W = H_L1W + (size_t)256*128;            // [128,256]  (h,l)
constexpr size_t H_TOTAL = H_P2W + (size_t)128*256 + 4096;
__device__ __align__(256) __half g_h[H_TOTAL];

// ---------------- streams/events ----------------
static cudaStream_t g_sP, g_sR, g_sS;
static cudaEvent_t g_evFork, g_evEnc, g_evParser, g_evS, g_evRec;
namespace {
struct StreamInit {
    StreamInit(){
        cudaStreamCreateWithFlags(&g_sP, cudaStreamNonBlocking);
        cudaStreamCreateWithFlags(&g_sR, cudaStreamNonBlocking);
        cudaStreamCreateWithFlags(&g_sS, cudaStreamNonBlocking);
        cudaEventCreateWithFlags(&g_evFork,   cudaEventDisableTiming);
        cudaEventCreateWithFlags(&g_evEnc,    cudaEventDisableTiming);
        cudaEventCreateWithFlags(&g_evParser, cudaEventDisableTiming);
        cudaEventCreateWithFlags(&g_evS,      cudaEventDisableTiming);
        cudaEventCreateWithFlags(&g_evRec,    cudaEventDisableTiming);
    }
};
StreamInit s_streamInit;
}

// ---------------- PTX helpers ----------------
__device__ __forceinline__ uint32_t smem_u32(const void* p){
    uint32_t a; asm("{ .reg .u64 t; cvta.to.shared.u64 t, %1; cvt.u32.u64 %0, t; }" : "=r"(a) : "l"(p)); return a;
}
__device__ __forceinline__ void cp_async16(uint32_t dst, const void* src){
    asm volatile("cp.async.cg.shared.global [%0], [%1], 16;" :: "r"(dst), "l"(src));
}
__device__ __forceinline__ void cp_commit(){ asm volatile("cp.async.commit_group;" ::: "memory"); }
__device__ __forceinline__ void cp_wait0(){ asm volatile("cp.async.wait_group 0;" ::: "memory"); }
__device__ __forceinline__ void ldmx4(uint32_t* r, uint32_t addr){
    asm volatile("ldmatrix.sync.aligned.m8n8.x4.shared.b16 {%0,%1,%2,%3}, [%4];"
        : "=r"(r[0]),"=r"(r[1]),"=r"(r[2]),"=r"(r[3]) : "r"(addr));
}
__device__ __forceinline__ void mma16816(float* d, const uint32_t* a, const uint32_t* b){
    asm volatile("mma.sync.aligned.m16n8k16.row.col.f32.f16.f16.f32 "
        "{%0,%1,%2,%3}, {%4,%5,%6,%7}, {%8,%9}, {%0,%1,%2,%3};"
        : "+f"(d[0]),"+f"(d[1]),"+f"(d[2]),"+f"(d[3])
        : "r"(a[0]),"r"(a[1]),"r"(a[2]),"r"(a[3]), "r"(b[0]),"r"(b[1]));
}

// ---------------- fp16 HMMA GEMM, BM=128/BN=128/BK=32, one sync per iter ----------------
__global__ void __launch_bounds__(256, 2)
mma_gemm(const __half* __restrict__ A, int lda,
         const __half* __restrict__ B, int ldb,
         const float* __restrict__ bias,
         float* __restrict__ C, int ldc,
         int M, int N, int Kp, int flags,
         int Nsplit, const float* __restrict__ bias2,
         float* __restrict__ C2, int ldc2, int flags2,
         int epimode, __half* __restrict__ SP, float* __restrict__ esqp)
{
    __shared__ __align__(128) __half As[2][128*32];
    __shared__ __align__(128) __half Bs[2][128*32];
    const int tid = threadIdx.x;
    const int lane = tid & 31, wid = tid >> 5;
    const int wm = wid >> 1, wn = wid & 1;
    const int bm = blockIdx.y * 128, bn = blockIdx.x * 128;
    const uint32_t as0 = smem_u32(As), bs0 = smem_u32(Bs);

    float acc[2][8][4];
#pragma unroll
    for (int i = 0; i < 2; i++)
#pragma unroll
        for (int j = 0; j < 8; j++)
#pragma unroll
            for (int k = 0; k < 4; k++) acc[i][j][k] = 0.f;

    const int a_row_l = lane & 15, a_cb = lane >> 4;
    const int g = lane >> 3, b_row_l = ((g >> 1) & 1) * 8 + (lane & 7), b_cb = g & 1;

    auto loadAB = [&](int buf, int k0){
#pragma unroll
        for (int j = 0; j < 2; j++){
            int u = tid * 2 + j;
            int row = u >> 2, c = u & 3;
            int cs = c ^ ((row >> 1) & 3);
            cp_async16(as0 + (uint32_t)(buf*8192 + row*64 + cs*16),
                       A + (size_t)(bm + row) * lda + k0 + c*8);
            cp_async16(bs0 + (uint32_t)(buf*8192 + row*64 + cs*16),
                       B + (size_t)(bn + row) * ldb + k0 + c*8);
        }
        cp_commit();
    };

    const int nk = Kp >> 5;
    loadAB(0, 0);
    for (int i = 0; i < nk; i++){
        const int buf = i & 1;
        cp_wait0();
        __syncthreads();
        if (i + 1 < nk) loadAB(buf ^ 1, (i+1) * 32);
#pragma unroll
        for (int kk = 0; kk < 2; kk++){
            uint32_t afr[2][4], bfr[4][4];
#pragma unroll
            for (int mi = 0; mi < 2; mi++){
                int row = wm*32 + mi*16 + a_row_l;
                int c = kk*2 + a_cb;
                int cs = c ^ ((row >> 1) & 3);
                ldmx4(afr[mi], as0 + (uint32_t)(buf*8192 + row*64 + cs*16));
            }
#pragma unroll
            for (int nh = 0; nh < 4; nh++){
                int row = wn*64 + nh*16 + b_row_l;
                int c = kk*2 + b_cb;
                int cs = c ^ ((row >> 1) & 3);
                ldmx4(bfr[nh], bs0 + (uint32_t)(buf*8192 + row*64 + cs*16));
            }
#pragma unroll
            for (int mi = 0; mi < 2; mi++)
#pragma unroll
                for (int ni = 0; ni < 8; ni++)
                    mma16816(acc[mi][ni], afr[mi], &bfr[ni>>1][(ni&1)*2]);
        }
    }

    if (epimode == 1){
        const bool is_es = (bn >= Nsplit);
        const float* bs = is_es ? bias2 : bias;
        const int cb = bn - (is_es ? Nsplit : 0) + wn*64;
        uint32_t* SPw = (uint32_t*)SP;
#pragma unroll
        for (int mi = 0; mi < 2; mi++){
#pragma unroll
            for (int h = 0; h < 2; h++){
                int row = bm + wm*32 + mi*16 + (lane >> 2) + h*8;
                bool rok = row < M;
                float sq = 0.f;
#pragma unroll
                for (int ni = 0; ni < 8; ni++){
                    int c = cb + ni*8 + (lane & 3)*2;
                    float v0 = acc[mi][ni][h*2+0] + bs[c];
                    float v1 = acc[mi][ni][h*2+1] + bs[c+1];
                    if (rok){
                        if (is_es){
                            C2[(size_t)row*ldc2 + c]   = v0;
                            C2[(size_t)row*ldc2 + c+1] = v1;
                            sq += v0*v0 + v1*v1;
                        }
                        __half h0 = __float2half(v0);
                        __half l0 = __float2half(v0 - __half2float(h0));
                        __half h1 = __float2half(v1);
                        __half l1 = __float2half(v1 - __half2float(h1));
                        size_t wi = (size_t)row*1024 + (is_es ? 512 : 0) + c;
                        SPw[wi]   = (uint32_t)__half_as_ushort(h0) | ((uint32_t)__half_as_ushort(l0) << 16);
                        SPw[wi+1] = (uint32_t)__half_as_ushort(h1) | ((uint32_t)__half_as_ushort(l1) << 16);
                    }
                }
                if (is_es){
                    sq += __shfl_xor_sync(0xffffffffu, sq, 1);
                    sq += __shfl_xor_sync(0xffffffffu, sq, 2);
                    if (rok && (lane & 3) == 0) atomicAdd(&esqp[row], sq);
                }
            }
        }
        return;
    }

    const float sc1 = (flags  & FL_SCALE) ? BN_S : 1.f;
    const float sc2 = (flags2 & FL_SCALE) ? BN_S : 1.f;
#pragma unroll
    for (int mi = 0; mi < 2; mi++){
#pragma unroll
        for (int ni = 0; ni < 8; ni++){
            int col = bn + wn*64 + ni*8 + (lane & 3) * 2;
#pragma unroll
            for (int h = 0; h < 2; h++){
                int row = bm + wm*32 + mi*16 + (lane >> 2) + h*8;
                if (row < M){
#pragma unroll
                    for (int q = 0; q < 2; q++){
                        int cc = col + q;
                        if (cc < N){
                            float v = acc[mi][ni][h*2 + q];
                            if (cc < Nsplit){
                                if (bias) v += bias[cc];
                                if (flags & FL_RELU) v = fmaxf(v, 0.f);
                                C[(size_t)row * ldc + cc] = v * sc1;
                            } else {
                                int c2 = cc - Nsplit;
                                if (bias2) v += bias2[c2];
                                if (flags2 & FL_RELU) v = fmaxf(v, 0.f);
                                C2[(size_t)row * ldc2 + c2] = v * sc2;
                            }
                        }
                    }
                }
            }
        }
    }
}

// ---------------- fused edge parser ----------------
constexpr int P_HROW = 264;
constexpr int P_HB   = 128 * P_HROW * 2;
constexpr int P_WOFF = P_HB;
constexpr int P_P1   = P_WOFF + 16384;
constexpr int P_P2B  = P_P1 + 2048;
constexpr int P_EACC = P_P2B + 512;
constexpr int PAR_SMEM = P_EACC + 1024 + 256;
__global__ void __launch_bounds__(256, 2)
parser_edge_kernel(const float* __restrict__ nif,
                   const float* __restrict__ p1w, const float* __restrict__ p1b,
                   const __half* __restrict__ W2s, const float* __restrict__ p2b,
                   float* __restrict__ dppA, float* __restrict__ naA, float* __restrict__ nbA)
{
    extern __shared__ char sm[];
    uint32_t* Hs32 = (uint32_t*)sm;
    const uint32_t base = smem_u32(sm);
    const uint32_t wsb  = base + P_WOFF;
    float* p1s  = (float*)(sm + P_P1);
    float* p2bs = (float*)(sm + P_P2B);
    float* eacc = (float*)(sm + P_EACC);

    const int tid = threadIdx.x, lane = tid & 31, wid = tid >> 5;
    const int wm = wid >> 1, wn = wid & 1;
    const int e0 = blockIdx.x * 64;

    for (int i = tid; i < 512; i += 256)
        p1s[i] = (i < 384) ? p1w[i] : p1b[i - 384];
    if (tid < 128) p2bs[tid] = p2b[tid];
    if (tid < 64) { eacc[tid*4] = 0.f; eacc[tid*4+1] = 0.f; eacc[tid*4+2] = 0.f; }
    __syncthreads();

    {
        int r = tid >> 1, hh = tid & 1;
        int e = e0 + (r >> 1), side = r & 1;
        const float* x = nif + (size_t)e*6 + side*3;
        float x0 = x[0], x1 = x[1], x2 = x[2];
#pragma unroll
        for (int j = 0; j < 64; j++){
            int ju = hh*64 + j;
            float v = fmaf(p1s[ju*3+2], x2, fmaf(p1s[ju*3+1], x1, fmaf(p1s[ju*3], x0, p1s[384+ju])));
            v = fmaxf(v, 0.f) * BN_S;
            uint32_t hb = (uint32_t)__half_as_ushort(__float2half(v));
            Hs32[r*(P_HROW/2) + ju] = hb | (hb << 16);
        }
    }

    auto loadW = [&](int buf, int k0){
#pragma unroll
        for (int j = 0; j < 2; j++){
            int u = tid*2 + j;
            int row = u >> 2, c = u & 3;
            int cs = c ^ ((row >> 1) & 3);
            cp_async16(wsb + (uint32_t)(buf*8192 + row*64 + cs*16),
                       W2s + (size_t)row*256 + k0 + c*8);
        }
        cp_commit();
    };
    loadW(0, 0);

    float acc[2][8][4];
#pragma unroll
    for (int i = 0; i < 2; i++)
#pragma unroll
        for (int j = 0; j < 8; j++)
#pragma unroll
            for (int k = 0; k < 4; k++) acc[i][j][k] = 0.f;

    const int a_row_l = lane & 15, a_cb = lane >> 4;
    const int g = lane >> 3, b_row_l = ((g>>1)&1)*8 + (lane&7), b_cb = g & 1;

    for (int i = 0; i < 8; i++){
        const int buf = i & 1;
        cp_wait0();
        __syncthreads();
        if (i + 1 < 8) loadW(buf ^ 1, (i+1)*32);
#pragma unroll
        for (int kk = 0; kk < 2; kk++){
            uint32_t afr[2][4], bfr[4][4];
#pragma unroll
            for (int mi = 0; mi < 2; mi++){
                int row = wm*32 + mi*16 + a_row_l;
                int chunk = (i*2 + kk)*2 + a_cb;
                ldmx4(afr[mi], base + (uint32_t)(row*(P_HROW*2) + chunk*16));
            }
#pragma unroll
            for (int nh = 0; nh < 4; nh++){
                int row = wn*64 + nh*16 + b_row_l;
                int c = kk*2 + b_cb;
                int cs = c ^ ((row >> 1) & 3);
                ldmx4(bfr[nh], wsb + (uint32_t)(buf*8192 + row*64 + cs*16));
            }
#pragma unroll
            for (int mi = 0; mi < 2; mi++)
#pragma unroll
                for (int ni = 0; ni < 8; ni++)
                    mma16816(acc[mi][ni], afr[mi], &bfr[ni>>1][(ni&1)*2]);
        }
    }

#pragma unroll
    for (int mi = 0; mi < 2; mi++){
#pragma unroll
        for (int h = 0; h < 2; h++){
            float pd = 0.f, pq = 0.f;
#pragma unroll
            for (int ni = 0; ni < 8; ni++){
#pragma unroll
                for (int q = 0; q < 2; q++){
                    int col = wn*64 + ni*8 + (lane & 3)*2 + q;
                    float p = acc[mi][ni][h*2 + q] + p2bs[col];
                    float pp = __shfl_xor_sync(0xffffffffu, p, 4);
                    pd += p * pp;
                    pq += p * p;
                }
            }
            pd += __shfl_xor_sync(0xffffffffu, pd, 1);
            pd += __shfl_xor_sync(0xffffffffu, pd, 2);
            pq += __shfl_xor_sync(0xffffffffu, pq, 1);
            pq += __shfl_xor_sync(0xffffffffu, pq, 2);
            float nbv = __shfl_xor_sync(0xffffffffu, pq, 4);
            if ((lane & 7) == 0){
                int row = wm*32 + mi*16 + (lane >> 2) + h*8;
                int el = row >> 1;
                atomicAdd(&eacc[el*4 + 0], pd);
                atomicAdd(&eacc[el*4 + 1], pq);
                atomicAdd(&eacc[el*4 + 2], nbv);
            }
        }
    }
    __syncthreads();
    if (tid < 64){
        int e = e0 + tid;
        dppA[e] = eacc[tid*4 + 0];
        naA[e]  = eacc[tid*4 + 1];
        nbA[e]  = eacc[tid*4 + 2];
    }
}

// ---------------- vectorized fp16 2-term split: 4 inputs/thread ----------------
// mode 0 = dup (h,h), mode 1 = (h,l). KB must be multiple of 8 (all call sites are).
__global__ void split_h(const float* __restrict__ src, int lds_, int rows, int K, int KB,
                        __half* __restrict__ dst, int ldd, int mode, float* __restrict__ esq0)
{
    int r = blockIdx.y;
    int t = blockIdx.x * blockDim.x + threadIdx.x;
    if (esq0 && t == 0 && r < rows) esq0[r] = 0.f;
    int kb = t * 8;
    if (kb >= KB) return;
    int k = t * 4;
    float4 x;
    const float* sp = src + (size_t)r * lds_;
    if (r < rows && k + 4 <= K) x = *(const float4*)(sp + k);
    else {
        x.x = (r < rows && k   < K) ? sp[k]   : 0.f;
        x.y = (r < rows && k+1 < K) ? sp[k+1] : 0.f;
        x.z = (r < rows && k+2 < K) ? sp[k+2] : 0.f;
        x.w = (r < rows && k+3 < K) ? sp[k+3] : 0.f;
    }
    uint4 o;
    {
        __half h0 = __float2half(x.x), h1 = __float2half(x.y);
        __half h2 = __float2half(x.z), h3 = __float2half(x.w);
        __half s0 = mode ? __float2half(x.x - __half2float(h0)) : h0;
        __half s1 = mode ? __float2half(x.y - __half2float(h1)) : h1;
        __half s2 = mode ? __float2half(x.z - __half2float(h2)) : h2;
        __half s3 = mode ? __float2half(x.w - __half2float(h3)) : h3;
        o.x = (uint32_t)__half_as_ushort(h0) | ((uint32_t)__half_as_ushort(s0) << 16);
        o.y = (uint32_t)__half_as_ushort(h1) | ((uint32_t)__half_as_ushort(s1) << 16);
        o.z = (uint32_t)__half_as_ushort(h2) | ((uint32_t)__half_as_ushort(s2) << 16);
        o.w = (uint32_t)__half_as_ushort(h3) | ((uint32_t)__half_as_ushort(s3) << 16);
    }
    *(uint4*)(dst + (size_t)r * ldd + kb) = o;
}

// ---------------- small GEMM ----------------
__global__ void gemm_small(const float* __restrict__ A, int lda,
                           const float* __restrict__ B, int ldb,
                           const float* __restrict__ bias,
                           float* __restrict__ C, int ldc,
                           int M, int N, int K, int flags)
{
    int idx = blockIdx.x * blockDim.x + threadIdx.x;
    if (idx >= M * N) return;
    int m = idx / N, n = idx - m * N;
    float s = bias ? bias[n] : 0.f;
    const float* a = A + (size_t)m * lda;
    const float* b = B + (size_t)n * ldb;
    for (int k = 0; k < K; k++) s = fmaf(a[k], b[k], s);
    if (flags & FL_RELU) s = fmaxf(s, 0.f);
    if (flags & FL_SCALE) s *= BN_S;
    C[(size_t)m * ldc + n] = s;
}

// ---------------- node/edge kernels ----------------
__global__ void edge_weight_kernel(const int* __restrict__ src, const int* __restrict__ tgt,
                                   const float* __restrict__ dppA, const float* __restrict__ naA,
                                   const float* __restrict__ nbA,
                                   const float* __restrict__ es, const float* __restrict__ es_sq,
                                   float* __restrict__ ew, float* __restrict__ deg)
{
    int w = (blockIdx.x * blockDim.x + threadIdx.x) >> 5;
    int lane = threadIdx.x & 31;
    if (w >= NE) return;
    int s = src[w], t = tgt[w];
    const float4* rs = (const float4*)(es + (size_t)s * EMBD);
    const float4* rt = (const float4*)(es + (size_t)t * EMBD);
    float des = 0.f;
#pragma unroll
    for (int i = lane; i < EMBD/4; i += 32) { float4 a = rs[i], b = rt[i]; des += a.x*b.x+a.y*b.y+a.z*b.z+a.w*b.w; }
#pragma unroll
    for (int o = 16; o; o >>= 1) des += __shfl_down_sync(0xffffffffu, des, o);
    if (lane == 0) {
        float n1 = fmaxf(sqrtf(naA[w] + es_sq[s]), 1e-8f);
        float n2 = fmaxf(sqrtf(nbA[w] + es_sq[t]), 1e-8f);
        float cw = ((dppA[w] + des) / (n1 * n2) + 1.f) * 0.5f;
        ew[w] = cw;
        atomicAdd(&deg[s], cw);
    }
}

// fused dis+norm
__global__ void norm_kernel(const int* __restrict__ src, const int* __restrict__ tgt,
                            const float* __restrict__ ew, const float* __restrict__ deg,
                            float* __restrict__ nrm)
{
    int e = blockIdx.x * blockDim.x + threadIdx.x;
    if (e >= NE) return;
    float ds = deg[src[e]], dt = deg[tgt[e]];
    float a = ds > 0.f ? rsqrtf(ds) : 0.f;
    float b = dt > 0.f ? rsqrtf(dt) : 0.f;
    nrm[e] = a * ew[e] * b;
}

// prop with float4 gathers + red.global.v4
__global__ void prop_kernel(const int* __restrict__ src, const int* __restrict__ tgt,
                            const float* __restrict__ nrm,
                            const float* __restrict__ Z, int ldz, int offz,
                            float* __restrict__ Out, int width, int lg)
{
    int idx = blockIdx.x * blockDim.x + threadIdx.x;
    if (idx >= (NE << lg)) return;
    int e = idx >> lg;
    int c = (idx & ((1 << lg) - 1)) * 4;
    float s = -nrm[e];
    float4 zv = *(const float4*)&Z[(size_t)src[e] * ldz + offz + c];
    float* o = &Out[(size_t)tgt[e] * width + c];
    asm volatile("red.global.v4.f32.add [%0], {%1, %2, %3, %4};"
                 :: "l"(o), "f"(s*zv.x), "f"(s*zv.y), "f"(s*zv.z), "f"(s*zv.w) : "memory");
}

__global__ void prep_cheb(const float* __restrict__ W, int in_dim, float* __restrict__ Wt)
{
    int idx = blockIdx.x * blockDim.x + threadIdx.x;
    if (idx >= 48 * in_dim) return;
    int n = idx / in_dim, i = idx - n * in_dim;
    float v;
    if (n < 16)       v = W[(0*in_dim + i)*16 + n] - W[(2*in_dim + i)*16 + n];
    else if (n < 32)  v = W[(1*in_dim + i)*16 + (n - 16)];
    else              v = W[(2*in_dim + i)*16 + (n - 32)];
    Wt[(size_t)n * in_dim + i] = v;
}

// fused combine
__global__ void combine_kernel(float* __restrict__ A48, float* __restrict__ V32,
                               float* __restrict__ P16,
                               const float* __restrict__ Wn,
                               __half* __restrict__ jkS, int layer)
{
    int idx = blockIdx.x * blockDim.x + threadIdx.x;
    if (idx >= NN * 16) return;
    int m = idx >> 4, c = idx & 15;
    int lane = threadIdx.x & 31;
    float v = A48[(size_t)m*48 + c] + V32[(size_t)m*32 + c] + 2.f * P16[(size_t)m*16 + c];
    v = fmaxf(v, 0.f);
    __half hi = __float2half(v);
    __half lo = __float2half(v - __half2float(hi));
    __half* d = jkS + (size_t)m*128 + 2*(layer*16 + c);
    d[0] = hi; d[1] = lo;

    if (layer < 3){
        int base = lane & 16;
        float hv[16];
#pragma unroll
        for (int k = 0; k < 16; k++)
            hv[k] = __shfl_sync(0xffffffffu, v, base | k);
#pragma unroll
        for (int j = 0; j < 3; j++){
            int n = 3*c + j;
            float s = 0.f;
            if (n < 16){
#pragma unroll
                for (int k = 0; k < 16; k++)
                    s = fmaf(hv[k], Wn[k*16 + n] - Wn[512 + k*16 + n], s);
            } else if (n < 32){
                int nn = n - 16;
#pragma unroll
                for (int k = 0; k < 16; k++)
                    s = fmaf(hv[k], Wn[256 + k*16 + nn], s);
            } else {
                int nn = n - 32;
#pragma unroll
                for (int k = 0; k < 16; k++)
                    s = fmaf(hv[k], Wn[512 + k*16 + nn], s);
            }
            A48[(size_t)m*48 + n] = s;
        }
        V32[(size_t)m*32 + c] = 0.f;
        V32[(size_t)m*32 + c + 16] = 0.f;
        P16[(size_t)m*16 + c] = 0.f;
    }
}

// ---------------- launch ----------------
extern "C" void kernel_launch(void* const* d_in, const int* in_sizes, int n_in,
                              void* d_out, int out_size)
{
    const float* img   = (const float*)d_in[0];
    const int*   eidx  = (const int*)d_in[1];
    const float* nif   = (const float*)d_in[2];
    const float* EI_w  = (const float*)d_in[3];
    const float* EI_b  = (const float*)d_in[4];
    const float* ES_w  = (const float*)d_in[5];
    const float* ES_b  = (const float*)d_in[6];
    const float* DE_w  = (const float*)d_in[7];
    const float* DE_b  = (const float*)d_in[8];
    const float* chw[4] = {(const float*)d_in[9], (const float*)d_in[10],
                           (const float*)d_in[11], (const float*)d_in[12]};
    const float* l1_w  = (const float*)d_in[13];
    const float* l1_b  = (const float*)d_in[14];
    const float* l2_w  = (const float*)d_in[15];
    const float* l2_b  = (const float*)d_in[16];
    const float* s1_w  = (const float*)d_in[17];
    const float* s1_b  = (const float*)d_in[18];
    const float* s2_w  = (const float*)d_in[19];
    const float* s2_b  = (const float*)d_in[20];
    const float* p1_w  = (const float*)d_in[21];
    const float* p1_b  = (const float*)d_in[22];
    const float* p2_w  = (const float*)d_in[23];
    const float* p2_b  = (const float*)d_in[24];

    float* F = nullptr; cudaGetSymbolAddress((void**)&F, g_f);
    __half* Hh = nullptr; cudaGetSymbolAddress((void**)&Hh, g_h);

    float* dpp = F + F_DPP; float* na  = F + F_NA;  float* nb  = F + F_NB;
    float* z   = F + F_Z;   float* A48 = F + F_A48; float* V32 = F + F_V32;
    float* P16 = F + F_P16; float* esq = F + F_ESQ; float* ew  = F + F_EW;
    float* deg = F + F_DEG; float* nrm = F + F_NRM; float* Wt  = F + F_WT;

    __half* imgS = Hh + H_IMG;  __half* EIwS = Hh + H_EIW;  __half* ESwS = Hh + H_ESW;
    __half* eies = Hh + H_EIES; __half* jkS  = Hh + H_JKS;  __half* DEwH = Hh + H_DEW;
    __half* s1wH = Hh + H_S1W;  __half* chH  = Hh + H_CH;   __half* l1wH = Hh + H_L1W;
    __half* p2wH = Hh + H_P2W;

    float* out_label = (float*)d_out;
    float* out_site  = out_label + (size_t)NN * 2;
    float* out_es    = out_site  + (size_t)NN * 20;
    float* out_rec   = out_es    + (size_t)NN * 512;

    const int* srcp = eidx;
    const int* tgtp = eidx + NE;

    dim3 blk(256);
    cudaFuncSetAttribute(parser_edge_kernel, cudaFuncAttributeMaxDynamicSharedMemorySize, PAR_SMEM);

    auto splitsH = [&](const float* s, int lds_, int rows, int rp, int K, int KB,
                       __half* d, int ldd, int mode, cudaStream_t st, float* esq0 = nullptr) {
        dim3 gg(CDIV(KB/8, 256), rp);
        split_h<<<gg, blk, 0, st>>>(s, lds_, rows, K, KB, d, ldd, mode, esq0);
    };

    // 1: p2w split, fork
    splitsH(p2_w, 128, 128, 128, 128, 256, p2wH, 256, 1, 0);
    cudaEventRecord(g_evFork, 0);

    // sP: parser (concurrent with encoder)
    cudaStreamWaitEvent(g_sP, g_evFork, 0);
    parser_edge_kernel<<<NE/64, blk, PAR_SMEM, g_sP>>>(nif, p1_w, p1_b, p2wH, p2_b, dpp, na, nb);
    cudaEventRecord(g_evParser, g_sP);

    // sR: DE weight split now; rec after encoder
    cudaStreamWaitEvent(g_sR, g_evFork, 0);
    splitsH(DE_w, 1024, 512, 512, 1024, 2048, DEwH, 2048, 0, g_sR);

    // sS: s1 + cheb0 weight splits now
    cudaStreamWaitEvent(g_sS, g_evFork, 0);
    splitsH(s1_w, 512, 256, 256, 512, 1024, s1wH, 1024, 0, g_sS);
    prep_cheb<<<CDIV(48*512,256), blk, 0, g_sS>>>(chw[0], 512, Wt);
    splitsH(Wt, 512, 48, 64, 512, 1024, chH, 1024, 0, g_sS);

    // main: remaining encoder deps + encoder (img split zeroes esq)
    cudaMemsetAsync(deg, 0, NN * sizeof(float));
    cudaMemsetAsync(V32, 0, (size_t)NN*48*sizeof(float));   // V32+P16 (layer 0)
    splitsH(l1_w, 64, 256, 256, 64, 128, l1wH, 128, 0, 0);
    splitsH(EI_w, IND, 512, 512, IND, 4032, EIwS, 4032, 0, 0);
    splitsH(ES_w, IND, 512, 512, IND, 4032, ESwS, 4032, 0, 0);
    splitsH(img, IND, NN, MP, IND, 4032, imgS, 4032, 1, 0, esq);

    mma_gemm<<<dim3(8,157), blk>>>(imgS, 4032, EIwS, 4032, EI_b, nullptr, 0,
                                   NN, 1024, 4032, 0, 512, ES_b, out_es, 512, 0,
                                   1, eies, esq);
    cudaEventRecord(g_evEnc, 0);

    // sR: reconstruct
    cudaStreamWaitEvent(g_sR, g_evEnc, 0);
    mma_gemm<<<dim3(4,157), blk, 0, g_sR>>>(eies, 2048, DEwH, 2048, DE_b, out_rec, 512,
                                   NN, 512, 2048, 0, 512, nullptr, nullptr, 0, 0,
                                   0, nullptr, nullptr);
    cudaEventRecord(g_evRec, g_sR);

    // sS: fused s1 + cheb0, site head
    cudaStreamWaitEvent(g_sS, g_evEnc, 0);
    mma_gemm<<<dim3(3,157), blk, 0, g_sS>>>(eies, 2048, s1wH, 1024, s1_b, z, 256,
                                   NN, 304, 1024, FL_RELU|FL_SCALE, 256, nullptr, A48, 48, 0,
                                   0, nullptr, nullptr);
    gemm_small<<<CDIV(NN*20,256), blk, 0, g_sS>>>(z, 256, s2_w, 256, s2_b, out_site, 20, NN, 20, 256, 0);
    cudaEventRecord(g_evS, g_sS);

    // main: edge chain (needs parser + encoder outputs)
    cudaStreamWaitEvent(0, g_evParser, 0);
    edge_weight_kernel<<<CDIV(NE*32,256), blk>>>(srcp, tgtp, dpp, na, nb, out_es, esq, ew, deg);
    norm_kernel<<<CDIV(NE,256), blk>>>(srcp, tgtp, ew, deg, nrm);

    // cheb loop (needs A48 from sS)
    cudaStreamWaitEvent(0, g_evS, 0);
    for (int layer = 0; layer < 4; layer++) {
        prop_kernel<<<CDIV(NE*8,256), blk>>>(srcp, tgtp, nrm, A48, 48, 16, V32, 32, 3);
        prop_kernel<<<CDIV(NE*4,256), blk>>>(srcp, tgtp, nrm, V32, 32, 16, P16, 16, 2);
        combine_kernel<<<CDIV(NN*16,256), blk>>>(A48, V32, P16,
                                                 (layer < 3) ? chw[layer+1] : chw[0], jkS, layer);
    }

    // label head
    mma_gemm<<<dim3(2,157), blk>>>(jkS, 128, l1wH, 128, l1_b, z, 256,
                                   NN, 256, 128, FL_RELU|FL_SCALE, 256, nullptr, nullptr, 0, 0,
                                   0, nullptr, nullptr);
    gemm_small<<<CDIV(NN*2,256), blk>>>(z, 256, l2_w, 256, l2_b, out_label, 2, NN, 2, 256, 0);

    cudaStreamWaitEvent(0, g_evRec, 0);
}

// round 17
// speedup vs baseline: 1.5031x; 1.3884x over previous
#include <cuda_runtime.h>
#include <cuda_fp16.h>
#include <math.h>
#include <stdint.h>

constexpr int NN   = 20000;
constexpr int NE   = 200000;
constexpr int IND  = 2000;
constexpr int EMBD = 512;
constexpr float BN_S = 0.9999950000374997f;
constexpr int MP = 20096;                 // 157*128
constexpr int KIMG = 2016;                // IND padded to 32
#define CDIV(a,b) (((a)+(b)-1)/(b))
constexpr int FL_RELU = 1, FL_SCALE = 2;

// ---------------- fp32 scratch ----------------
constexpr size_t F_DPP = 0;
constexpr size_t F_NA  = F_DPP + NE;
constexpr size_t F_NB  = F_NA  + NE;
constexpr size_t F_Z   = F_NB  + NE;                        // [NN,256]
constexpr size_t F_A48 = F_Z   + (size_t)NN*256;
constexpr size_t F_V32 = F_A48 + (size_t)NN*48;
constexpr size_t F_P16 = F_V32 + (size_t)NN*32;             // adjacent to V32
constexpr size_t F_ESQ = F_P16 + (size_t)NN*16;
constexpr size_t F_EW  = F_ESQ + NN;
constexpr size_t F_DEG = F_EW  + NE;
constexpr size_t F_NRM = F_DEG + NN;
constexpr size_t F_WT  = F_NRM + NE;
constexpr size_t F_TOTAL = F_WT + (size_t)48*512;
__device__ __align__(256) float g_f[F_TOTAL];

// ---------------- fp16 arena (pure fp16, no splits) ----------------
constexpr size_t H_IMG = 0;                                  // [MP,2016]
constexpr size_t H_EIW = H_IMG + (size_t)MP*KIMG;            // [512,2016]
constexpr size_t H_ESW = H_EIW + (size_t)512*KIMG;           // contiguous after EIW
constexpr size_t H_EIES= H_ESW + (size_t)512*KIMG;           // [MP,1024]: ei 0-511, es 512-1023
constexpr size_t H_JKS = H_EIES+ (size_t)MP*1024;            // [MP,64]
constexpr size_t H_DEW = H_JKS + (size_t)MP*64;              // [512,1024]
constexpr size_t H_S1W = H_DEW + (size_t)512*1024;           // [256,512]
constexpr size_t H_CH  = H_S1W + (size_t)256*512;            // [64,512] contiguous after S1W
constexpr size_t H_L1W = H_CH  + (size_t)64*512;             // [256,64]
constexpr size_t H_P2W = H_L1W + (size_t)256*64;             // [128,128]
constexpr size_t H_TOTAL = H_P2W + (size_t)128*128 + 4096;
__device__ __align__(256) __half g_h[H_TOTAL];

// ---------------- streams/events ----------------
static cudaStream_t g_sP, g_sR, g_sS;
static cudaEvent_t g_evFork, g_evEnc, g_evParser, g_evS, g_evRec;
namespace {
struct StreamInit {
    StreamInit(){
        cudaStreamCreateWithFlags(&g_sP, cudaStreamNonBlocking);
        cudaStreamCreateWithFlags(&g_sR, cudaStreamNonBlocking);
        cudaStreamCreateWithFlags(&g_sS, cudaStreamNonBlocking);
        cudaEventCreateWithFlags(&g_evFork,   cudaEventDisableTiming);
        cudaEventCreateWithFlags(&g_evEnc,    cudaEventDisableTiming);
        cudaEventCreateWithFlags(&g_evParser, cudaEventDisableTiming);
        cudaEventCreateWithFlags(&g_evS,      cudaEventDisableTiming);
        cudaEventCreateWithFlags(&g_evRec,    cudaEventDisableTiming);
    }
};
StreamInit s_streamInit;
}

// ---------------- PTX helpers ----------------
__device__ __forceinline__ uint32_t smem_u32(const void* p){
    uint32_t a; asm("{ .reg .u64 t; cvta.to.shared.u64 t, %1; cvt.u32.u64 %0, t; }" : "=r"(a) : "l"(p)); return a;
}
__device__ __forceinline__ void cp_async16(uint32_t dst, const void* src){
    asm volatile("cp.async.cg.shared.global [%0], [%1], 16;" :: "r"(dst), "l"(src));
}
__device__ __forceinline__ void cp_commit(){ asm volatile("cp.async.commit_group;" ::: "memory"); }
__device__ __forceinline__ void cp_wait0(){ asm volatile("cp.async.wait_group 0;" ::: "memory"); }
__device__ __forceinline__ void ldmx4(uint32_t* r, uint32_t addr){
    asm volatile("ldmatrix.sync.aligned.m8n8.x4.shared.b16 {%0,%1,%2,%3}, [%4];"
        : "=r"(r[0]),"=r"(r[1]),"=r"(r[2]),"=r"(r[3]) : "r"(addr));
}
__device__ __forceinline__ void mma16816(float* d, const uint32_t* a, const uint32_t* b){
    asm volatile("mma.sync.aligned.m16n8k16.row.col.f32.f16.f16.f32 "
        "{%0,%1,%2,%3}, {%4,%5,%6,%7}, {%8,%9}, {%0,%1,%2,%3};"
        : "+f"(d[0]),"+f"(d[1]),"+f"(d[2]),"+f"(d[3])
        : "r"(a[0]),"r"(a[1]),"r"(a[2]),"r"(a[3]), "r"(b[0]),"r"(b[1]));
}

// ---------------- fp16 HMMA GEMM, BM=128/BN=128/BK=32, one sync per iter ----------------
__global__ void __launch_bounds__(256, 2)
mma_gemm(const __half* __restrict__ A, int lda,
         const __half* __restrict__ B, int ldb,
         const float* __restrict__ bias,
         float* __restrict__ C, int ldc,
         int M, int N, int Kp, int flags,
         int Nsplit, const float* __restrict__ bias2,
         float* __restrict__ C2, int ldc2, int flags2,
         int epimode, __half* __restrict__ SP, float* __restrict__ esqp)
{
    __shared__ __align__(128) __half As[2][128*32];
    __shared__ __align__(128) __half Bs[2][128*32];
    const int tid = threadIdx.x;
    const int lane = tid & 31, wid = tid >> 5;
    const int wm = wid >> 1, wn = wid & 1;
    const int bm = blockIdx.y * 128, bn = blockIdx.x * 128;
    const uint32_t as0 = smem_u32(As), bs0 = smem_u32(Bs);

    float acc[2][8][4];
#pragma unroll
    for (int i = 0; i < 2; i++)
#pragma unroll
        for (int j = 0; j < 8; j++)
#pragma unroll
            for (int k = 0; k < 4; k++) acc[i][j][k] = 0.f;

    const int a_row_l = lane & 15, a_cb = lane >> 4;
    const int g = lane >> 3, b_row_l = ((g >> 1) & 1) * 8 + (lane & 7), b_cb = g & 1;

    auto loadAB = [&](int buf, int k0){
#pragma unroll
        for (int j = 0; j < 2; j++){
            int u = tid * 2 + j;
            int row = u >> 2, c = u & 3;
            int cs = c ^ ((row >> 1) & 3);
            cp_async16(as0 + (uint32_t)(buf*8192 + row*64 + cs*16),
                       A + (size_t)(bm + row) * lda + k0 + c*8);
            cp_async16(bs0 + (uint32_t)(buf*8192 + row*64 + cs*16),
                       B + (size_t)(bn + row) * ldb + k0 + c*8);
        }
        cp_commit();
    };

    const int nk = Kp >> 5;
    loadAB(0, 0);
    for (int i = 0; i < nk; i++){
        const int buf = i & 1;
        cp_wait0();
        __syncthreads();
        if (i + 1 < nk) loadAB(buf ^ 1, (i+1) * 32);
#pragma unroll
        for (int kk = 0; kk < 2; kk++){
            uint32_t afr[2][4], bfr[4][4];
#pragma unroll
            for (int mi = 0; mi < 2; mi++){
                int row = wm*32 + mi*16 + a_row_l;
                int c = kk*2 + a_cb;
                int cs = c ^ ((row >> 1) & 3);
                ldmx4(afr[mi], as0 + (uint32_t)(buf*8192 + row*64 + cs*16));
            }
#pragma unroll
            for (int nh = 0; nh < 4; nh++){
                int row = wn*64 + nh*16 + b_row_l;
                int c = kk*2 + b_cb;
                int cs = c ^ ((row >> 1) & 3);
                ldmx4(bfr[nh], bs0 + (uint32_t)(buf*8192 + row*64 + cs*16));
            }
#pragma unroll
            for (int mi = 0; mi < 2; mi++)
#pragma unroll
                for (int ni = 0; ni < 8; ni++)
                    mma16816(acc[mi][ni], afr[mi], &bfr[ni>>1][(ni&1)*2]);
        }
    }

    if (epimode == 1){
        // encoder: fp16 eies [M,1024] (ei cols 0-511 via !is_es, es 512-1023) + out_es fp32 + esq
        const bool is_es = (bn >= Nsplit);
        const float* bs = is_es ? bias2 : bias;
        const int cb = bn - (is_es ? Nsplit : 0) + wn*64;
        uint32_t* SPw = (uint32_t*)SP;
#pragma unroll
        for (int mi = 0; mi < 2; mi++){
#pragma unroll
            for (int h = 0; h < 2; h++){
                int row = bm + wm*32 + mi*16 + (lane >> 2) + h*8;
                bool rok = row < M;
                float sq = 0.f;
#pragma unroll
                for (int ni = 0; ni < 8; ni++){
                    int c = cb + ni*8 + (lane & 3)*2;
                    float v0 = acc[mi][ni][h*2+0] + bs[c];
                    float v1 = acc[mi][ni][h*2+1] + bs[c+1];
                    if (rok){
                        if (is_es){
                            C2[(size_t)row*ldc2 + c]   = v0;
                            C2[(size_t)row*ldc2 + c+1] = v1;
                            sq += v0*v0 + v1*v1;
                        }
                        uint32_t h0 = __half_as_ushort(__float2half(v0));
                        uint32_t h1 = __half_as_ushort(__float2half(v1));
                        SPw[(size_t)row*512 + (is_es ? 256 : 0) + (c >> 1)] = h0 | (h1 << 16);
                    }
                }
                if (is_es){
                    sq += __shfl_xor_sync(0xffffffffu, sq, 1);
                    sq += __shfl_xor_sync(0xffffffffu, sq, 2);
                    if (rok && (lane & 3) == 0) atomicAdd(&esqp[row], sq);
                }
            }
        }
        return;
    }

    const float sc1 = (flags  & FL_SCALE) ? BN_S : 1.f;
    const float sc2 = (flags2 & FL_SCALE) ? BN_S : 1.f;
#pragma unroll
    for (int mi = 0; mi < 2; mi++){
#pragma unroll
        for (int ni = 0; ni < 8; ni++){
            int col = bn + wn*64 + ni*8 + (lane & 3) * 2;
#pragma unroll
            for (int h = 0; h < 2; h++){
                int row = bm + wm*32 + mi*16 + (lane >> 2) + h*8;
                if (row < M){
#pragma unroll
                    for (int q = 0; q < 2; q++){
                        int cc = col + q;
                        if (cc < N){
                            float v = acc[mi][ni][h*2 + q];
                            if (cc < Nsplit){
                                if (bias) v += bias[cc];
                                if (flags & FL_RELU) v = fmaxf(v, 0.f);
                                C[(size_t)row * ldc + cc] = v * sc1;
                            } else {
                                int c2 = cc - Nsplit;
                                if (bias2) v += bias2[c2];
                                if (flags2 & FL_RELU) v = fmaxf(v, 0.f);
                                C2[(size_t)row * ldc2 + c2] = v * sc2;
                            }
                        }
                    }
                }
            }
        }
    }
}

// ---------------- fused edge parser: pure fp16, K=128 ----------------
constexpr int P_HROW = 136;                     // 128 + 8 pad halves (272B rows, conflict-free)
constexpr int P_HB   = 128 * P_HROW * 2;        // 34816
constexpr int P_WOFF = P_HB;
constexpr int P_P1   = P_WOFF + 16384;
constexpr int P_P2B  = P_P1 + 2048;
constexpr int P_EACC = P_P2B + 512;
constexpr int PAR_SMEM = P_EACC + 1024 + 256;
__global__ void __launch_bounds__(256, 2)
parser_edge_kernel(const float* __restrict__ nif,
                   const float* __restrict__ p1w, const float* __restrict__ p1b,
                   const __half* __restrict__ W2s, const float* __restrict__ p2b,
                   float* __restrict__ dppA, float* __restrict__ naA, float* __restrict__ nbA)
{
    extern __shared__ char sm[];
    uint32_t* Hs32 = (uint32_t*)sm;
    const uint32_t base = smem_u32(sm);
    const uint32_t wsb  = base + P_WOFF;
    float* p1s  = (float*)(sm + P_P1);
    float* p2bs = (float*)(sm + P_P2B);
    float* eacc = (float*)(sm + P_EACC);

    const int tid = threadIdx.x, lane = tid & 31, wid = tid >> 5;
    const int wm = wid >> 1, wn = wid & 1;
    const int e0 = blockIdx.x * 64;

    for (int i = tid; i < 512; i += 256)
        p1s[i] = (i < 384) ? p1w[i] : p1b[i - 384];
    if (tid < 128) p2bs[tid] = p2b[tid];
    if (tid < 64) { eacc[tid*4] = 0.f; eacc[tid*4+1] = 0.f; eacc[tid*4+2] = 0.f; }
    __syncthreads();

    // generate H: row r (edge e side), 128 hidden values, packed as 64 uint32
    {
        int r = tid >> 1, hh = tid & 1;
        int e = e0 + (r >> 1), side = r & 1;
        const float* x = nif + (size_t)e*6 + side*3;
        float x0 = x[0], x1 = x[1], x2 = x[2];
#pragma unroll
        for (int j = 0; j < 32; j++){
            int j0 = hh*64 + 2*j, j1 = j0 + 1;
            float v0 = fmaf(p1s[j0*3+2], x2, fmaf(p1s[j0*3+1], x1, fmaf(p1s[j0*3], x0, p1s[384+j0])));
            float v1 = fmaf(p1s[j1*3+2], x2, fmaf(p1s[j1*3+1], x1, fmaf(p1s[j1*3], x0, p1s[384+j1])));
            v0 = fmaxf(v0, 0.f) * BN_S;
            v1 = fmaxf(v1, 0.f) * BN_S;
            uint32_t h0 = __half_as_ushort(__float2half(v0));
            uint32_t h1 = __half_as_ushort(__float2half(v1));
            Hs32[r*(P_HROW/2) + hh*32 + j] = h0 | (h1 << 16);
        }
    }

    auto loadW = [&](int buf, int k0){
#pragma unroll
        for (int j = 0; j < 2; j++){
            int u = tid*2 + j;
            int row = u >> 2, c = u & 3;
            int cs = c ^ ((row >> 1) & 3);
            cp_async16(wsb + (uint32_t)(buf*8192 + row*64 + cs*16),
                       W2s + (size_t)row*128 + k0 + c*8);
        }
        cp_commit();
    };
    loadW(0, 0);

    float acc[2][8][4];
#pragma unroll
    for (int i = 0; i < 2; i++)
#pragma unroll
        for (int j = 0; j < 8; j++)
#pragma unroll
            for (int k = 0; k < 4; k++) acc[i][j][k] = 0.f;

    const int a_row_l = lane & 15, a_cb = lane >> 4;
    const int g = lane >> 3, b_row_l = ((g>>1)&1)*8 + (lane&7), b_cb = g & 1;

    for (int i = 0; i < 4; i++){
        const int buf = i & 1;
        cp_wait0();
        __syncthreads();
        if (i + 1 < 4) loadW(buf ^ 1, (i+1)*32);
#pragma unroll
        for (int kk = 0; kk < 2; kk++){
            uint32_t afr[2][4], bfr[4][4];
#pragma unroll
            for (int mi = 0; mi < 2; mi++){
                int row = wm*32 + mi*16 + a_row_l;
                int chunk = (i*2 + kk)*2 + a_cb;
                ldmx4(afr[mi], base + (uint32_t)(row*(P_HROW*2) + chunk*16));
            }
#pragma unroll
            for (int nh = 0; nh < 4; nh++){
                int row = wn*64 + nh*16 + b_row_l;
                int c = kk*2 + b_cb;
                int cs = c ^ ((row >> 1) & 3);
                ldmx4(bfr[nh], wsb + (uint32_t)(buf*8192 + row*64 + cs*16));
            }
#pragma unroll
            for (int mi = 0; mi < 2; mi++)
#pragma unroll
                for (int ni = 0; ni < 8; ni++)
                    mma16816(acc[mi][ni], afr[mi], &bfr[ni>>1][(ni&1)*2]);
        }
    }

#pragma unroll
    for (int mi = 0; mi < 2; mi++){
#pragma unroll
        for (int h = 0; h < 2; h++){
            float pd = 0.f, pq = 0.f;
#pragma unroll
            for (int ni = 0; ni < 8; ni++){
#pragma unroll
                for (int q = 0; q < 2; q++){
                    int col = wn*64 + ni*8 + (lane & 3)*2 + q;
                    float p = acc[mi][ni][h*2 + q] + p2bs[col];
                    float pp = __shfl_xor_sync(0xffffffffu, p, 4);
                    pd += p * pp;
                    pq += p * p;
                }
            }
            pd += __shfl_xor_sync(0xffffffffu, pd, 1);
            pd += __shfl_xor_sync(0xffffffffu, pd, 2);
            pq += __shfl_xor_sync(0xffffffffu, pq, 1);
            pq += __shfl_xor_sync(0xffffffffu, pq, 2);
            float nbv = __shfl_xor_sync(0xffffffffu, pq, 4);
            if ((lane & 7) == 0){
                int row = wm*32 + mi*16 + (lane >> 2) + h*8;
                int el = row >> 1;
                atomicAdd(&eacc[el*4 + 0], pd);
                atomicAdd(&eacc[el*4 + 1], pq);
                atomicAdd(&eacc[el*4 + 2], nbv);
            }
        }
    }
    __syncthreads();
    if (tid < 64){
        int e = e0 + tid;
        dppA[e] = eacc[tid*4 + 0];
        naA[e]  = eacc[tid*4 + 1];
        nbA[e]  = eacc[tid*4 + 2];
    }
}

// ---------------- fp32 -> fp16 convert, 4 elems/thread ----------------
__global__ void conv_h(const float* __restrict__ src, int lds_, int rows, int K, int KB,
                       __half* __restrict__ dst, int ldd, float* __restrict__ esq0)
{
    int r = blockIdx.y;
    int t = blockIdx.x * blockDim.x + threadIdx.x;
    if (esq0 && t == 0 && r < rows) esq0[r] = 0.f;
    int k = t * 4;
    if (k >= KB) return;
    float4 x;
    const float* sp = src + (size_t)r * lds_;
    if (r < rows && k + 4 <= K) x = *(const float4*)(sp + k);
    else {
        x.x = (r < rows && k   < K) ? sp[k]   : 0.f;
        x.y = (r < rows && k+1 < K) ? sp[k+1] : 0.f;
        x.z = (r < rows && k+2 < K) ? sp[k+2] : 0.f;
        x.w = (r < rows && k+3 < K) ? sp[k+3] : 0.f;
    }
    uint2 o;
    o.x = (uint32_t)__half_as_ushort(__float2half(x.x)) | ((uint32_t)__half_as_ushort(__float2half(x.y)) << 16);
    o.y = (uint32_t)__half_as_ushort(__float2half(x.z)) | ((uint32_t)__half_as_ushort(__float2half(x.w)) << 16);
    *(uint2*)(dst + (size_t)r * ldd + k) = o;
}

// ---------------- small GEMM ----------------
__global__ void gemm_small(const float* __restrict__ A, int lda,
                           const float* __restrict__ B, int ldb,
                           const float* __restrict__ bias,
                           float* __restrict__ C, int ldc,
                           int M, int N, int K, int flags)
{
    int idx = blockIdx.x * blockDim.x + threadIdx.x;
    if (idx >= M * N) return;
    int m = idx / N, n = idx - m * N;
    float s = bias ? bias[n] : 0.f;
    const float* a = A + (size_t)m * lda;
    const float* b = B + (size_t)n * ldb;
    for (int k = 0; k < K; k++) s = fmaf(a[k], b[k], s);
    if (flags & FL_RELU) s = fmaxf(s, 0.f);
    if (flags & FL_SCALE) s *= BN_S;
    C[(size_t)m * ldc + n] = s;
}

// ---------------- node/edge kernels ----------------
__global__ void edge_weight_kernel(const int* __restrict__ src, const int* __restrict__ tgt,
                                   const float* __restrict__ dppA, const float* __restrict__ naA,
                                   const float* __restrict__ nbA,
                                   const float* __restrict__ es, const float* __restrict__ es_sq,
                                   float* __restrict__ ew, float* __restrict__ deg)
{
    int w = (blockIdx.x * blockDim.x + threadIdx.x) >> 5;
    int lane = threadIdx.x & 31;
    if (w >= NE) return;
    int s = src[w], t = tgt[w];
    const float4* rs = (const float4*)(es + (size_t)s * EMBD);
    const float4* rt = (const float4*)(es + (size_t)t * EMBD);
    float des = 0.f;
#pragma unroll
    for (int i = lane; i < EMBD/4; i += 32) { float4 a = rs[i], b = rt[i]; des += a.x*b.x+a.y*b.y+a.z*b.z+a.w*b.w; }
#pragma unroll
    for (int o = 16; o; o >>= 1) des += __shfl_down_sync(0xffffffffu, des, o);
    if (lane == 0) {
        float n1 = fmaxf(sqrtf(naA[w] + es_sq[s]), 1e-8f);
        float n2 = fmaxf(sqrtf(nbA[w] + es_sq[t]), 1e-8f);
        float cw = ((dppA[w] + des) / (n1 * n2) + 1.f) * 0.5f;
        ew[w] = cw;
        atomicAdd(&deg[s], cw);
    }
}

__global__ void norm_kernel(const int* __restrict__ src, const int* __restrict__ tgt,
                            const float* __restrict__ ew, const float* __restrict__ deg,
                            float* __restrict__ nrm)
{
    int e = blockIdx.x * blockDim.x + threadIdx.x;
    if (e >= NE) return;
    float ds = deg[src[e]], dt = deg[tgt[e]];
    float a = ds > 0.f ? rsqrtf(ds) : 0.f;
    float b = dt > 0.f ? rsqrtf(dt) : 0.f;
    nrm[e] = a * ew[e] * b;
}

__global__ void prop_kernel(const int* __restrict__ src, const int* __restrict__ tgt,
                            const float* __restrict__ nrm,
                            const float* __restrict__ Z, int ldz, int offz,
                            float* __restrict__ Out, int width, int lg)
{
    int idx = blockIdx.x * blockDim.x + threadIdx.x;
    if (idx >= (NE << lg)) return;
    int e = idx >> lg;
    int c = (idx & ((1 << lg) - 1)) * 4;
    float s = -nrm[e];
    float4 zv = *(const float4*)&Z[(size_t)src[e] * ldz + offz + c];
    float* o = &Out[(size_t)tgt[e] * width + c];
    asm volatile("red.global.v4.f32.add [%0], {%1, %2, %3, %4};"
                 :: "l"(o), "f"(s*zv.x), "f"(s*zv.y), "f"(s*zv.z), "f"(s*zv.w) : "memory");
}

__global__ void prep_cheb(const float* __restrict__ W, int in_dim, float* __restrict__ Wt)
{
    int idx = blockIdx.x * blockDim.x + threadIdx.x;
    if (idx >= 48 * in_dim) return;
    int n = idx / in_dim, i = idx - n * in_dim;
    float v;
    if (n < 16)       v = W[(0*in_dim + i)*16 + n] - W[(2*in_dim + i)*16 + n];
    else if (n < 32)  v = W[(1*in_dim + i)*16 + (n - 16)];
    else              v = W[(2*in_dim + i)*16 + (n - 32)];
    Wt[(size_t)n * in_dim + i] = v;
}

// fused combine: jkS single fp16, next-layer A48 via shfl, zero V32/P16
__global__ void combine_kernel(float* __restrict__ A48, float* __restrict__ V32,
                               float* __restrict__ P16,
                               const float* __restrict__ Wn,
                               __half* __restrict__ jkS, int layer)
{
    int idx = blockIdx.x * blockDim.x + threadIdx.x;
    if (idx >= NN * 16) return;
    int m = idx >> 4, c = idx & 15;
    int lane = threadIdx.x & 31;
    float v = A48[(size_t)m*48 + c] + V32[(size_t)m*32 + c] + 2.f * P16[(size_t)m*16 + c];
    v = fmaxf(v, 0.f);
    jkS[(size_t)m*64 + layer*16 + c] = __float2half(v);

    if (layer < 3){
        int base = lane & 16;
        float hv[16];
#pragma unroll
        for (int k = 0; k < 16; k++)
            hv[k] = __shfl_sync(0xffffffffu, v, base | k);
#pragma unroll
        for (int j = 0; j < 3; j++){
            int n = 3*c + j;
            float s = 0.f;
            if (n < 16){
#pragma unroll
                for (int k = 0; k < 16; k++)
                    s = fmaf(hv[k], Wn[k*16 + n] - Wn[512 + k*16 + n], s);
            } else if (n < 32){
                int nn = n - 16;
#pragma unroll
                for (int k = 0; k < 16; k++)
                    s = fmaf(hv[k], Wn[256 + k*16 + nn], s);
            } else {
                int nn = n - 32;
#pragma unroll
                for (int k = 0; k < 16; k++)
                    s = fmaf(hv[k], Wn[512 + k*16 + nn], s);
            }
            A48[(size_t)m*48 + n] = s;
        }
        V32[(size_t)m*32 + c] = 0.f;
        V32[(size_t)m*32 + c + 16] = 0.f;
        P16[(size_t)m*16 + c] = 0.f;
    }
}

// ---------------- launch ----------------
extern "C" void kernel_launch(void* const* d_in, const int* in_sizes, int n_in,
                              void* d_out, int out_size)
{
    const float* img   = (const float*)d_in[0];
    const int*   eidx  = (const int*)d_in[1];
    const float* nif   = (const float*)d_in[2];
    const float* EI_w  = (const float*)d_in[3];
    const float* EI_b  = (const float*)d_in[4];
    const float* ES_w  = (const float*)d_in[5];
    const float* ES_b  = (const float*)d_in[6];
    const float* DE_w  = (const float*)d_in[7];
    const float* DE_b  = (const float*)d_in[8];
    const float* chw[4] = {(const float*)d_in[9], (const float*)d_in[10],
                           (const float*)d_in[11], (const float*)d_in[12]};
    const float* l1_w  = (const float*)d_in[13];
    const float* l1_b  = (const float*)d_in[14];
    const float* l2_w  = (const float*)d_in[15];
    const float* l2_b  = (const float*)d_in[16];
    const float* s1_w  = (const float*)d_in[17];
    const float* s1_b  = (const float*)d_in[18];
    const float* s2_w  = (const float*)d_in[19];
    const float* s2_b  = (const float*)d_in[20];
    const float* p1_w  = (const float*)d_in[21];
    const float* p1_b  = (const float*)d_in[22];
    const float* p2_w  = (const float*)d_in[23];
    const float* p2_b  = (const float*)d_in[24];

    float* F = nullptr; cudaGetSymbolAddress((void**)&F, g_f);
    __half* Hh = nullptr; cudaGetSymbolAddress((void**)&Hh, g_h);

    float* dpp = F + F_DPP; float* na  = F + F_NA;  float* nb  = F + F_NB;
    float* z   = F + F_Z;   float* A48 = F + F_A48; float* V32 = F + F_V32;
    float* P16 = F + F_P16; float* esq = F + F_ESQ; float* ew  = F + F_EW;
    float* deg = F + F_DEG; float* nrm = F + F_NRM; float* Wt  = F + F_WT;

    __half* imgH = Hh + H_IMG;  __half* EIwH = Hh + H_EIW;  __half* ESwH = Hh + H_ESW;
    __half* eies = Hh + H_EIES; __half* jkS  = Hh + H_JKS;  __half* DEwH = Hh + H_DEW;
    __half* s1wH = Hh + H_S1W;  __half* chH  = Hh + H_CH;   __half* l1wH = Hh + H_L1W;
    __half* p2wH = Hh + H_P2W;

    float* out_label = (float*)d_out;
    float* out_site  = out_label + (size_t)NN * 2;
    float* out_es    = out_site  + (size_t)NN * 20;
    float* out_rec   = out_es    + (size_t)NN * 512;

    const int* srcp = eidx;
    const int* tgtp = eidx + NE;

    dim3 blk(256);
    cudaFuncSetAttribute(parser_edge_kernel, cudaFuncAttributeMaxDynamicSharedMemorySize, PAR_SMEM);

    auto convH = [&](const float* s, int lds_, int rows, int rp, int K, int KB,
                     __half* d, int ldd, cudaStream_t st, float* esq0 = nullptr) {
        dim3 gg(CDIV(KB/4, 256), rp);
        conv_h<<<gg, blk, 0, st>>>(s, lds_, rows, K, KB, d, ldd, esq0);
    };

    // 1: p2w convert, fork
    convH(p2_w, 128, 128, 128, 128, 128, p2wH, 128, 0);
    cudaEventRecord(g_evFork, 0);

    // sP: parser (shares machine with encoder)
    cudaStreamWaitEvent(g_sP, g_evFork, 0);
    parser_edge_kernel<<<NE/64, blk, PAR_SMEM, g_sP>>>(nif, p1_w, p1_b, p2wH, p2_b, dpp, na, nb);
    cudaEventRecord(g_evParser, g_sP);

    // sR: DE weight convert now; rec after encoder
    cudaStreamWaitEvent(g_sR, g_evFork, 0);
    convH(DE_w, 1024, 512, 512, 1024, 1024, DEwH, 1024, g_sR);

    // sS: s1 + cheb0 weight prep now
    cudaStreamWaitEvent(g_sS, g_evFork, 0);
    convH(s1_w, 512, 256, 256, 512, 512, s1wH, 512, g_sS);
    prep_cheb<<<CDIV(48*512,256), blk, 0, g_sS>>>(chw[0], 512, Wt);
    convH(Wt, 512, 48, 64, 512, 512, chH, 512, g_sS);

    // main: remaining encoder deps + encoder (img convert zeroes esq)
    cudaMemsetAsync(deg, 0, NN * sizeof(float));
    cudaMemsetAsync(V32, 0, (size_t)NN*48*sizeof(float));   // V32+P16 (layer 0)
    convH(l1_w, 64, 256, 256, 64, 64, l1wH, 64, 0);
    convH(EI_w, IND, 512, 512, IND, KIMG, EIwH, KIMG, 0);
    convH(ES_w, IND, 512, 512, IND, KIMG, ESwH, KIMG, 0);
    convH(img, IND, NN, MP, IND, KIMG, imgH, KIMG, 0, esq);

    mma_gemm<<<dim3(8,157), blk>>>(imgH, KIMG, EIwH, KIMG, EI_b, nullptr, 0,
                                   NN, 1024, KIMG, 0, 512, ES_b, out_es, 512, 0,
                                   1, eies, esq);
    cudaEventRecord(g_evEnc, 0);

    // sR: reconstruct (Kp=1024)
    cudaStreamWaitEvent(g_sR, g_evEnc, 0);
    mma_gemm<<<dim3(4,157), blk, 0, g_sR>>>(eies, 1024, DEwH, 1024, DE_b, out_rec, 512,
                                   NN, 512, 1024, 0, 512, nullptr, nullptr, 0, 0,
                                   0, nullptr, nullptr);
    cudaEventRecord(g_evRec, g_sR);

    // sS: fused s1 + cheb0 (Kp=512, ei half), site head
    cudaStreamWaitEvent(g_sS, g_evEnc, 0);
    mma_gemm<<<dim3(3,157), blk, 0, g_sS>>>(eies, 1024, s1wH, 512, s1_b, z, 256,
                                   NN, 304, 512, FL_RELU|FL_SCALE, 256, nullptr, A48, 48, 0,
                                   0, nullptr, nullptr);
    gemm_small<<<CDIV(NN*20,256), blk, 0, g_sS>>>(z, 256, s2_w, 256, s2_b, out_site, 20, NN, 20, 256, 0);
    cudaEventRecord(g_evS, g_sS);

    // main: edge chain
    cudaStreamWaitEvent(0, g_evParser, 0);
    edge_weight_kernel<<<CDIV(NE*32,256), blk>>>(srcp, tgtp, dpp, na, nb, out_es, esq, ew, deg);
    norm_kernel<<<CDIV(NE,256), blk>>>(srcp, tgtp, ew, deg, nrm);

    // cheb loop
    cudaStreamWaitEvent(0, g_evS, 0);
    for (int layer = 0; layer < 4; layer++) {
        prop_kernel<<<CDIV(NE*8,256), blk>>>(srcp, tgtp, nrm, A48, 48, 16, V32, 32, 3);
        prop_kernel<<<CDIV(NE*4,256), blk>>>(srcp, tgtp, nrm, V32, 32, 16, P16, 16, 2);
        combine_kernel<<<CDIV(NN*16,256), blk>>>(A48, V32, P16,
                                                 (layer < 3) ? chw[layer+1] : chw[0], jkS, layer);
    }

    // label head (Kp=64)
    mma_gemm<<<dim3(2,157), blk>>>(jkS, 64, l1wH, 64, l1_b, z, 256,
                                   NN, 256, 64, FL_RELU|FL_SCALE, 256, nullptr, nullptr, 0, 0,
                                   0, nullptr, nullptr);
    gemm_small<<<CDIV(NN*2,256), blk>>>(z, 256, l2_w, 256, l2_b, out_label, 2, NN, 2, 256, 0);

    cudaStreamWaitEvent(0, g_evRec, 0);
}